// round 8
// baseline (speedup 1.0000x reference)
#include <cuda_runtime.h>
#include <math.h>
#include <cstdint>

#define BB 4
#define NN 8192

__device__ float g_tproj[BB*256];
__device__ float g_pbest[4*BB*NN];
__device__ int   g_pidx [4*BB*NN];
// int8 planes: [N][256] bytes, k-words permuted within 32B groups
__device__ int8_t g_w1h[4*256*256], g_w1l[4*256*256];
__device__ int8_t g_w2h[4*256*256], g_w2l[4*256*256];
__device__ int8_t g_owh[128*256],   g_owl[128*256];
__device__ float  g_ws1[4*256], g_ws2[4*256], g_wso[128];

__device__ __forceinline__ uint32_t smem_to_u32(const void* p) {
    uint32_t a;
    asm("{ .reg .u64 t; cvta.to.shared.u64 t, %1; cvt.u32.u64 %0, t; }" : "=r"(a) : "l"(p));
    return a;
}
__device__ __forceinline__ void cp_async16(uint32_t d, const void* s) {
    asm volatile("cp.async.ca.shared.global [%0], [%1], 16;" :: "r"(d), "l"(s) : "memory");
}
#define CP_COMMIT() asm volatile("cp.async.commit_group;" ::: "memory")
template<int N> __device__ __forceinline__ void cp_wait() {
    asm volatile("cp.async.wait_group %0;" :: "n"(N) : "memory");
}
#define LD2(r0, r1, ba) asm volatile("ld.shared.v2.u32 {%0,%1}, [%2];" : "=r"(r0), "=r"(r1) : "r"(ba))

__device__ __forceinline__ void mmai8(int c[4], const uint32_t a[4], const uint32_t b[2]) {
    asm volatile("mma.sync.aligned.m16n8k32.row.col.s32.s8.s8.s32 "
        "{%0,%1,%2,%3},{%4,%5,%6,%7},{%8,%9},{%0,%1,%2,%3};"
        : "+r"(c[0]),"+r"(c[1]),"+r"(c[2]),"+r"(c[3])
        : "r"(a[0]),"r"(a[1]),"r"(a[2]),"r"(a[3]),"r"(b[0]),"r"(b[1]));
}
__device__ __forceinline__ float silu(float x) { return x / (1.0f + __expf(-x)); }
__device__ __forceinline__ float comb(int hh, int xx) { return fmaf(65536.f, (float)hh, 256.f*(float)xx); }
// byte position of k within row: 4-byte words permuted within 32B groups
__device__ __forceinline__ int offk(int k) {
    int w = (k >> 2) & 7;
    return (k & ~31) + (((w & 3) << 1) | (w >> 2)) * 4 + (k & 3);
}

// smem byte offsets
#define B_XF 0
#define B_XH 66560
#define B_XL 83968
#define B_HH 101376
#define B_HL 118784
#define B_WB 136192
#define B_CV 209920
#define B_B1 210944
#define B_GA 211968
#define B_BE 212992
#define B_B2 214016
#define B_SWA 215040
#define B_SWB 216064
#define B_FEAT 217088
#define B_SRS 218624
#define B_SRQ 220672
#define B_MU 222720
#define B_RS 222976
#define B_SAX 223232
#define B_SAH 223488
#define B_INV 223744
#define SMEM_BYTES 224000

// ===== weight quantize: per-n scale, int16 -> hi/lo int8 planes =====
__global__ void quantw_kernel(const float* __restrict__ ly_w1,
                              const float* __restrict__ ly_w2,
                              const float* __restrict__ out_w1)
{
    int gw = blockIdx.x*8 + (threadIdx.x >> 5);
    int lane = threadIdx.x & 31;
    int m = gw >> 8, n = gw & 255;
    const float* src; int8_t *dh, *dl; float* sc; int N = 256;
    if (m < 4)      { src = ly_w1 + m*65536;     dh = g_w1h + m*65536; dl = g_w1l + m*65536; sc = g_ws1 + m*256; }
    else if (m < 8) { src = ly_w2 + (m-4)*65536; dh = g_w2h + (m-4)*65536; dl = g_w2l + (m-4)*65536; sc = g_ws2 + (m-4)*256; }
    else            { if (n >= 128) return; src = out_w1; dh = g_owh; dl = g_owl; sc = g_wso; N = 128; }
    float vals[8], mx = 0.f;
    #pragma unroll
    for (int i = 0; i < 8; i++) { vals[i] = src[(lane + i*32)*N + n]; mx = fmaxf(mx, fabsf(vals[i])); }
    #pragma unroll
    for (int o = 16; o > 0; o >>= 1) mx = fmaxf(mx, __shfl_xor_sync(~0u, mx, o));
    if (lane == 0) sc[n] = mx * (1.f/32512.f);
    float iv = mx > 0.f ? 32512.f/mx : 0.f;
    #pragma unroll
    for (int i = 0; i < 8; i++) {
        int q = __float2int_rn(vals[i] * iv);
        int vh = (q + 128) >> 8, vl = q - (vh << 8);
        int o = n*256 + offk(lane + i*32);
        dh[o] = (int8_t)vh; dl[o] = (int8_t)vl;
    }
}

// ===== time embedding =====
__global__ void temb_kernel(const int* __restrict__ timesteps,
                            const float* __restrict__ te_w1, const float* __restrict__ te_b1,
                            const float* __restrict__ te_w2, const float* __restrict__ te_b2,
                            const float* __restrict__ tp_w,  const float* __restrict__ tp_b)
{
    __shared__ float emb[128], h1[512], h2[512];
    int b = blockIdx.x, t = threadIdx.x;
    if (t < 64) {
        float fr = expf((float)t * (-logf(10000.0f) / 63.0f));
        float an = (float)timesteps[b] * fr;
        emb[t] = sinf(an); emb[t+64] = cosf(an);
    }
    __syncthreads();
    { float a = te_b1[t];
      #pragma unroll 4
      for (int k = 0; k < 128; k++) a = fmaf(emb[k], te_w1[k*512+t], a);
      h1[t] = a / (1.0f + expf(-a)); }
    __syncthreads();
    { float a = te_b2[t];
      #pragma unroll 4
      for (int k = 0; k < 512; k++) a = fmaf(h1[k], te_w2[k*512+t], a);
      h2[t] = a; }
    __syncthreads();
    if (t < 256) {
        float a = tp_b[t];
        #pragma unroll 4
        for (int k = 0; k < 512; k++) a = fmaf(h2[k], tp_w[k*256+t], a);
        g_tproj[b*256+t] = a;
    }
}

// ===== nearest neighbor =====
#define TSZ 2048
__global__ void nn_kernel(const float* __restrict__ noisy, const float* __restrict__ target)
{
    __shared__ float4 ts[TSZ];
    int b = blockIdx.x >> 8, chunk = (blockIdx.x >> 2) & 63, slice = blockIdx.x & 3;
    int t = threadIdx.x;
    const float4* tg4 = (const float4*)(target + ((size_t)b*NN + (size_t)slice*TSZ) * 3);
    for (int p4 = t; p4 < TSZ/4; p4 += 128) {
        float4 v0 = tg4[3*p4], v1 = tg4[3*p4+1], v2 = tg4[3*p4+2];
        ts[4*p4+0] = make_float4(v0.x, v0.y, v0.z, 0.5f*(v0.x*v0.x + v0.y*v0.y + v0.z*v0.z));
        ts[4*p4+1] = make_float4(v0.w, v1.x, v1.y, 0.5f*(v0.w*v0.w + v1.x*v1.x + v1.y*v1.y));
        ts[4*p4+2] = make_float4(v1.z, v1.w, v2.x, 0.5f*(v1.z*v1.z + v1.w*v1.w + v2.x*v2.x));
        ts[4*p4+3] = make_float4(v2.y, v2.z, v2.w, 0.5f*(v2.y*v2.y + v2.z*v2.z + v2.w*v2.w));
    }
    __syncthreads();
    int p = chunk*128 + t;
    const float* q = noisy + ((size_t)b*NN + p) * 3;
    float qx = -q[0], qy = -q[1], qz = -q[2];
    float best = INFINITY; int bidx = 0;
    #pragma unroll 8
    for (int j = 0; j < TSZ; j++) {
        float4 vv = ts[j];
        float e = fmaf(qx, vv.x, vv.w); e = fmaf(qy, vv.y, e); e = fmaf(qz, vv.z, e);
        if (e < best) { best = e; bidx = j; }
    }
    int pi = b*NN + p;
    g_pbest[slice*(BB*NN) + pi] = best;
    g_pidx [slice*(BB*NN) + pi] = slice*TSZ + bidx;
}

// ===== int8 fused MLP =====
__device__ __forceinline__ void loadW(uint32_t su, int buf,
                                      const int8_t* __restrict__ gh,
                                      const int8_t* __restrict__ gl,
                                      int kc, int nRows, int t)
{
    uint32_t base = su + B_WB + buf*36864;
    int tot = nRows*8;
    #pragma unroll
    for (int i = t; i < tot; i += 512) {
        int n = i >> 3, j = i & 7;
        if (j < 4) cp_async16(base + (uint32_t)(n*144 + j*16),          gh + n*256 + kc*64 + j*16);
        else       cp_async16(base + (uint32_t)(n*144 + 64 + (j-4)*16), gl + n*256 + kc*64 + (j-4)*16);
    }
}

template<int NT>   // 4 => N=256, 2 => N=128. Tile kc=0 pre-issued by caller.
__device__ __forceinline__ void gemm_i8(uint32_t su, int AHo, int ALo,
                                        const int8_t* __restrict__ gh,
                                        const int8_t* __restrict__ gl,
                                        int nRows, int chh[2][NT][4], int cx[2][NT][4],
                                        int t, int wm, int wn, int g, int tt)
{
    #pragma unroll 1
    for (int kc = 0; kc < 4; kc++) {
        __syncthreads();
        if (kc < 3) { loadW(su, (kc+1)&1, gh, gl, kc+1, nRows, t); CP_COMMIT(); cp_wait<1>(); }
        else cp_wait<0>();
        __syncthreads();
        uint32_t WB = su + B_WB + (kc&1)*36864;
        #pragma unroll
        for (int cc = 0; cc < 2; cc++) {
            int cb = kc*64 + cc*32;
            uint32_t ah[2][4], al[2][4], bh[NT][2], bl[NT][2];
            #pragma unroll
            for (int mi = 0; mi < 2; mi++) {
                int r = wm*32 + mi*16 + g;
                uint32_t a0 = su + AHo + r*272 + cb + tt*8;
                LD2(ah[mi][0], ah[mi][2], a0);
                LD2(ah[mi][1], ah[mi][3], a0 + 8*272);
                uint32_t c0 = su + ALo + r*272 + cb + tt*8;
                LD2(al[mi][0], al[mi][2], c0);
                LD2(al[mi][1], al[mi][3], c0 + 8*272);
            }
            #pragma unroll
            for (int nt = 0; nt < NT; nt++) {
                int n = wn*(NT*8) + nt*8 + g;
                uint32_t ib = WB + (uint32_t)(n*144 + cc*32 + tt*8);
                LD2(bh[nt][0], bh[nt][1], ib);
                LD2(bl[nt][0], bl[nt][1], ib + 64);
            }
            #pragma unroll
            for (int mi = 0; mi < 2; mi++)
                #pragma unroll
                for (int nt = 0; nt < NT; nt++) {
                    mmai8(chh[mi][nt], ah[mi], bh[nt]);
                    mmai8(cx[mi][nt],  ah[mi], bl[nt]);
                    mmai8(cx[mi][nt],  al[mi], bh[nt]);
                }
        }
    }
    __syncthreads();
}

// rowmax-scale quantize v -> int8 hi/lo planes; scale vec into savec
__device__ __forceinline__ void rq_store(float v[2][4][4], float M[2][2], char* smc,
                                         float* srs, float* invv, float* savec,
                                         int PLH, int PLL, int wm, int wn, int g, int tt, int t)
{
    #pragma unroll
    for (int mi = 0; mi < 2; mi++)
        #pragma unroll
        for (int h = 0; h < 2; h++) {
            float m_ = M[mi][h];
            m_ = fmaxf(m_, __shfl_xor_sync(~0u, m_, 1));
            m_ = fmaxf(m_, __shfl_xor_sync(~0u, m_, 2));
            if (tt == 0) srs[(wm*32 + mi*16 + h*8 + g)*8 + wn] = m_;
        }
    __syncthreads();
    if (t < 64) {
        float m_ = srs[t*8];
        #pragma unroll
        for (int i = 1; i < 8; i++) m_ = fmaxf(m_, srs[t*8 + i]);
        savec[t] = m_ * (1.f/32512.f);
        invv[t]  = m_ > 0.f ? 32512.f/m_ : 0.f;
    }
    __syncthreads();
    #pragma unroll
    for (int mi = 0; mi < 2; mi++)
        #pragma unroll
        for (int h = 0; h < 2; h++) {
            int r = wm*32 + mi*16 + h*8 + g;
            float iv = invv[r];
            #pragma unroll
            for (int nt = 0; nt < 4; nt++) {
                int bc = wn*32 + nt*8 + 2*tt;
                int q0 = __float2int_rn(v[mi][nt][2*h]   * iv);
                int q1 = __float2int_rn(v[mi][nt][2*h+1] * iv);
                int h0 = (q0 + 128) >> 8, h1 = (q1 + 128) >> 8;
                int l0 = q0 - (h0 << 8),  l1 = q1 - (h1 << 8);
                int ob = r*272 + offk(bc);
                *(uint16_t*)(smc + PLH + ob) = (uint16_t)((h0 & 255) | ((h1 & 255) << 8));
                *(uint16_t*)(smc + PLL + ob) = (uint16_t)((l0 & 255) | ((l1 & 255) << 8));
            }
        }
}

__global__ __launch_bounds__(512, 1)
void mlp_i8(const float* __restrict__ noisy, const float* __restrict__ target,
            const float* __restrict__ in_w,  const float* __restrict__ in_b,
            const float* __restrict__ ly_b1, const float* __restrict__ ly_g,
            const float* __restrict__ ly_be, const float* __restrict__ ly_b2,
            const float* __restrict__ out_b1, const float* __restrict__ out_w2,
            const float* __restrict__ out_b2, float* __restrict__ out)
{
    extern __shared__ float sm[];
    char* smc = (char*)sm;
    uint32_t su = smem_to_u32(sm);
    int t = threadIdx.x, lane = t & 31, w = t >> 5;
    int wm = w & 1, wn = w >> 1, g = lane >> 2, tt = lane & 3;
    int b = blockIdx.x >> 7, row0 = (blockIdx.x & 127) << 6;

    float* xf  = sm + B_XF/4;   float* cv   = sm + B_CV/4;
    float* b1s = sm + B_B1/4;   float* gas  = sm + B_GA/4;
    float* bes = sm + B_BE/4;   float* b2s  = sm + B_B2/4;
    float* swa = sm + B_SWA/4;  float* swb  = sm + B_SWB/4;
    float* feat= sm + B_FEAT/4; float* srs  = sm + B_SRS/4;
    float* srq = sm + B_SRQ/4;  float* mus  = sm + B_MU/4;
    float* rss = sm + B_RS/4;   float* sax  = sm + B_SAX/4;
    float* sah = sm + B_SAH/4;  float* invv = sm + B_INV/4;

    if (t < 256) { cv[t] = in_b[t] + g_tproj[b*256 + t]; swa[t] = g_ws1[t]; }
    loadW(su, 0, g_w1h, g_w1l, 0, 256, t); CP_COMMIT();
    if (t < 64) {   // fused nn_reduce
        int pi = b*NN + row0 + t;
        float best = g_pbest[pi]; int bi = g_pidx[pi];
        #pragma unroll
        for (int s = 1; s < 4; s++) {
            float vv = g_pbest[s*(BB*NN) + pi];
            if (vv < best) { best = vv; bi = g_pidx[s*(BB*NN) + pi]; }
        }
        const float* tc = target + ((size_t)b*NN + bi)*3;
        feat[t*6+0] = noisy[(size_t)pi*3+0]; feat[t*6+1] = noisy[(size_t)pi*3+1]; feat[t*6+2] = noisy[(size_t)pi*3+2];
        feat[t*6+3] = tc[0]; feat[t*6+4] = tc[1]; feat[t*6+5] = tc[2];
    }
    __syncthreads();

    float v[2][4][4];
    // ---- input: x = feat @ in_w + cv; write fp32 XF + quantize planes ----
    {
        float M[2][2] = {{0,0},{0,0}};
        #pragma unroll
        for (int mi = 0; mi < 2; mi++)
            #pragma unroll
            for (int nt = 0; nt < 4; nt++) {
                int bc = wn*32 + nt*8 + 2*tt;
                #pragma unroll
                for (int e = 0; e < 4; e++) {
                    int r = wm*32 + mi*16 + (e>>1)*8 + g, c = bc + (e&1);
                    float a = cv[c];
                    #pragma unroll
                    for (int k = 0; k < 6; k++) a = fmaf(feat[r*6+k], in_w[k*256+c], a);
                    v[mi][nt][e] = a;
                    xf[r*260 + c] = a;
                    M[mi][e>>1] = fmaxf(M[mi][e>>1], fabsf(a));
                }
            }
        rq_store(v, M, smc, srs, invv, sax, B_XH, B_XL, wm, wn, g, tt, t);
    }

    int chh[2][4][4], cx[2][4][4];
    // ---- residual layers ----
    #pragma unroll 1
    for (int lay = 0; lay < 4; lay++) {
        if (t < 256) {
            b1s[t] = ly_b1[lay*256+t]; gas[t] = ly_g[lay*256+t];
            bes[t] = ly_be[lay*256+t]; b2s[t] = ly_b2[lay*256+t];
        }
        #pragma unroll
        for (int mi = 0; mi < 2; mi++)
            #pragma unroll
            for (int nt = 0; nt < 4; nt++)
                #pragma unroll
                for (int e = 0; e < 4; e++) { chh[mi][nt][e] = 0; cx[mi][nt][e] = 0; }
        gemm_i8<4>(su, B_XH, B_XL, g_w1h + lay*65536, g_w1l + lay*65536, 256, chh, cx, t, wm, wn, g, tt);

        loadW(su, 0, g_w2h + lay*65536, g_w2l + lay*65536, 0, 256, t); CP_COMMIT();
        if (t < 256) swb[t] = g_ws2[lay*256 + t];

        // epilogue1: recombine + b1, LN stats
        float S[2][2] = {{0,0},{0,0}}, Q[2][2] = {{0,0},{0,0}};
        #pragma unroll
        for (int mi = 0; mi < 2; mi++) {
            float sx0 = sax[wm*32 + mi*16 + g], sx1 = sax[wm*32 + mi*16 + 8 + g];
            #pragma unroll
            for (int nt = 0; nt < 4; nt++) {
                int bc = wn*32 + nt*8 + 2*tt;
                float w0 = swa[bc], w1 = swa[bc+1];
                float v0 = fmaf(sx0*w0, comb(chh[mi][nt][0], cx[mi][nt][0]), b1s[bc]);
                float v1 = fmaf(sx0*w1, comb(chh[mi][nt][1], cx[mi][nt][1]), b1s[bc+1]);
                float v2 = fmaf(sx1*w0, comb(chh[mi][nt][2], cx[mi][nt][2]), b1s[bc]);
                float v3 = fmaf(sx1*w1, comb(chh[mi][nt][3], cx[mi][nt][3]), b1s[bc+1]);
                v[mi][nt][0]=v0; v[mi][nt][1]=v1; v[mi][nt][2]=v2; v[mi][nt][3]=v3;
                S[mi][0] += v0+v1; Q[mi][0] = fmaf(v0,v0,fmaf(v1,v1,Q[mi][0]));
                S[mi][1] += v2+v3; Q[mi][1] = fmaf(v2,v2,fmaf(v3,v3,Q[mi][1]));
            }
        }
        #pragma unroll
        for (int mi = 0; mi < 2; mi++)
            #pragma unroll
            for (int h = 0; h < 2; h++) {
                float s = S[mi][h], q = Q[mi][h];
                s += __shfl_xor_sync(~0u, s, 1); s += __shfl_xor_sync(~0u, s, 2);
                q += __shfl_xor_sync(~0u, q, 1); q += __shfl_xor_sync(~0u, q, 2);
                if (tt == 0) { int r = wm*32+mi*16+h*8+g; srs[r*8+wn] = s; srq[r*8+wn] = q; }
            }
        __syncthreads();
        if (t < 64) {
            float s = 0.f, q = 0.f;
            #pragma unroll
            for (int i = 0; i < 8; i++) { s += srs[t*8+i]; q += srq[t*8+i]; }
            float mu = s * (1.f/256.f);
            rss[t] = rsqrtf(fmaf(-mu, mu, q * (1.f/256.f)) + 1e-5f);
            mus[t] = mu;
        }
        __syncthreads();
        float M[2][2] = {{0,0},{0,0}};
        #pragma unroll
        for (int mi = 0; mi < 2; mi++)
            #pragma unroll
            for (int h = 0; h < 2; h++) {
                int r = wm*32 + mi*16 + h*8 + g;
                float mu = mus[r], rs = rss[r];
                #pragma unroll
                for (int nt = 0; nt < 4; nt++) {
                    int bc = wn*32 + nt*8 + 2*tt;
                    float h0 = silu(fmaf((v[mi][nt][2*h]   - mu)*rs, gas[bc],   bes[bc]));
                    float h1 = silu(fmaf((v[mi][nt][2*h+1] - mu)*rs, gas[bc+1], bes[bc+1]));
                    v[mi][nt][2*h] = h0; v[mi][nt][2*h+1] = h1;
                    M[mi][h] = fmaxf(M[mi][h], fmaxf(fabsf(h0), fabsf(h1)));
                }
            }
        rq_store(v, M, smc, srs, invv, sah, B_HH, B_HL, wm, wn, g, tt, t);

        // GEMM2
        #pragma unroll
        for (int mi = 0; mi < 2; mi++)
            #pragma unroll
            for (int nt = 0; nt < 4; nt++)
                #pragma unroll
                for (int e = 0; e < 4; e++) { chh[mi][nt][e] = 0; cx[mi][nt][e] = 0; }
        gemm_i8<4>(su, B_HH, B_HL, g_w2h + lay*65536, g_w2l + lay*65536, 256, chh, cx, t, wm, wn, g, tt);

        if (lay < 3) {
            loadW(su, 0, g_w1h + (lay+1)*65536, g_w1l + (lay+1)*65536, 0, 256, t);
            if (t < 256) swa[t] = g_ws1[(lay+1)*256 + t];
        } else {
            loadW(su, 0, g_owh, g_owl, 0, 128, t);
            if (t < 128) swa[t] = g_wso[t];
        }
        CP_COMMIT();

        // epilogue2: x(fp32) += delta + b2; requantize x planes
        float M2[2][2] = {{0,0},{0,0}};
        #pragma unroll
        for (int mi = 0; mi < 2; mi++) {
            int r0 = wm*32 + mi*16 + g;
            float sh0 = sah[r0], sh1 = sah[r0+8];
            #pragma unroll
            for (int nt = 0; nt < 4; nt++) {
                int bc = wn*32 + nt*8 + 2*tt;
                float w0 = swb[bc], w1 = swb[bc+1];
                float v0 = xf[r0*260 + bc]       + fmaf(sh0*w0, comb(chh[mi][nt][0], cx[mi][nt][0]), b2s[bc]);
                float v1 = xf[r0*260 + bc + 1]   + fmaf(sh0*w1, comb(chh[mi][nt][1], cx[mi][nt][1]), b2s[bc+1]);
                float v2 = xf[(r0+8)*260 + bc]   + fmaf(sh1*w0, comb(chh[mi][nt][2], cx[mi][nt][2]), b2s[bc]);
                float v3 = xf[(r0+8)*260 + bc+1] + fmaf(sh1*w1, comb(chh[mi][nt][3], cx[mi][nt][3]), b2s[bc+1]);
                xf[r0*260 + bc] = v0;     xf[r0*260 + bc + 1] = v1;
                xf[(r0+8)*260 + bc] = v2; xf[(r0+8)*260 + bc + 1] = v3;
                v[mi][nt][0]=v0; v[mi][nt][1]=v1; v[mi][nt][2]=v2; v[mi][nt][3]=v3;
                M2[mi][0] = fmaxf(M2[mi][0], fmaxf(fabsf(v0), fabsf(v1)));
                M2[mi][1] = fmaxf(M2[mi][1], fmaxf(fabsf(v2), fabsf(v3)));
            }
        }
        rq_store(v, M2, smc, srs, invv, sax, B_XH, B_XL, wm, wn, g, tt, t);
    }

    // ---- head GEMM (N=128) ----
    {
        int ch2[2][2][4], cx2[2][2][4];
        #pragma unroll
        for (int mi = 0; mi < 2; mi++)
            #pragma unroll
            for (int nt = 0; nt < 2; nt++)
                #pragma unroll
                for (int e = 0; e < 4; e++) { ch2[mi][nt][e] = 0; cx2[mi][nt][e] = 0; }
        gemm_i8<2>(su, B_XH, B_XL, g_owh, g_owl, 128, ch2, cx2, t, wm, wn, g, tt);
        // y1 = silu(recombine + out_b1) -> fp32 [64][132] in XF region
        #pragma unroll
        for (int mi = 0; mi < 2; mi++) {
            int r0 = wm*32 + mi*16 + g;
            float sx0 = sax[r0], sx1 = sax[r0+8];
            #pragma unroll
            for (int nt = 0; nt < 2; nt++) {
                int bc = wn*16 + nt*8 + 2*tt;
                float w0 = swa[bc], w1 = swa[bc+1];
                xf[r0*132 + bc]       = silu(fmaf(sx0*w0, comb(ch2[mi][nt][0], cx2[mi][nt][0]), out_b1[bc]));
                xf[r0*132 + bc + 1]   = silu(fmaf(sx0*w1, comb(ch2[mi][nt][1], cx2[mi][nt][1]), out_b1[bc+1]));
                xf[(r0+8)*132 + bc]   = silu(fmaf(sx1*w0, comb(ch2[mi][nt][2], cx2[mi][nt][2]), out_b1[bc]));
                xf[(r0+8)*132 + bc+1] = silu(fmaf(sx1*w1, comb(ch2[mi][nt][3], cx2[mi][nt][3]), out_b1[bc+1]));
            }
        }
    }
    __syncthreads();

    // ---- final: score = y1 @ out_w2 + out_b2 (128 -> 3, fp32) ----
    if (t < 192) {
        int rr = t / 3, p = t - rr*3;
        float a = out_b2[p];
        const float* y = xf + rr*132;
        #pragma unroll 8
        for (int k = 0; k < 128; k++) a = fmaf(y[k], out_w2[k*3 + p], a);
        out[(size_t)((b*NN + row0 + rr)*3 + p)] = a;
    }
}

// =====================================================================
extern "C" void kernel_launch(void* const* d_in, const int* in_sizes, int n_in,
                              void* d_out, int out_size)
{
    const float* noisy  = (const float*)d_in[0];
    const float* target = (const float*)d_in[1];
    const int*   tsteps = (const int*)  d_in[2];
    const float* te_w1  = (const float*)d_in[3];
    const float* te_b1  = (const float*)d_in[4];
    const float* te_w2  = (const float*)d_in[5];
    const float* te_b2  = (const float*)d_in[6];
    const float* tp_w   = (const float*)d_in[7];
    const float* tp_b   = (const float*)d_in[8];
    const float* in_w   = (const float*)d_in[9];
    const float* in_b   = (const float*)d_in[10];
    const float* ly_w1  = (const float*)d_in[11];
    const float* ly_b1  = (const float*)d_in[12];
    const float* ly_g   = (const float*)d_in[13];
    const float* ly_be  = (const float*)d_in[14];
    const float* ly_w2  = (const float*)d_in[15];
    const float* ly_b2  = (const float*)d_in[16];
    const float* out_w1 = (const float*)d_in[17];
    const float* out_b1 = (const float*)d_in[18];
    const float* out_w2 = (const float*)d_in[19];
    const float* out_b2 = (const float*)d_in[20];
    float* out = (float*)d_out;

    cudaFuncSetAttribute(mlp_i8, cudaFuncAttributeMaxDynamicSharedMemorySize, SMEM_BYTES);

    quantw_kernel<<<288, 256>>>(ly_w1, ly_w2, out_w1);
    temb_kernel<<<4, 512>>>(tsteps, te_w1, te_b1, te_w2, te_b2, tp_w, tp_b);
    nn_kernel<<<1024, 128>>>(noisy, target);
    mlp_i8<<<512, 512, SMEM_BYTES>>>(noisy, target, in_w, in_b,
                                     ly_b1, ly_g, ly_be, ly_b2,
                                     out_b1, out_w2, out_b2, out);
}

// round 9
// speedup vs baseline: 1.6972x; 1.6972x over previous
#include <cuda_runtime.h>
#include <cuda_fp16.h>
#include <math.h>
#include <cstdint>

#define BB 4
#define NN 8192

// ---------------- device scratch ----------------
__device__ float g_tproj[BB*256];
__device__ float g_pbest[4*BB*NN];
__device__ int   g_pidx [4*BB*NN];
// fp16 weight planes: [N][128] u32 (2 f16/u32 along K), k-pairs permuted in 8-groups
// hi = f16(W);  lo = f16((W - hi)*2048)
__device__ uint32_t g_w1h[4*256*128], g_w1l[4*256*128];
__device__ uint32_t g_w2h[4*256*128], g_w2l[4*256*128];
__device__ uint32_t g_owh[128*128],   g_owl[128*128];

// ================= helpers =================
__device__ __forceinline__ uint32_t smem_to_u32(const void* p) {
    uint32_t a;
    asm("{ .reg .u64 t; cvta.to.shared.u64 t, %1; cvt.u32.u64 %0, t; }" : "=r"(a) : "l"(p));
    return a;
}
__device__ __forceinline__ void cp_async16(uint32_t d, const void* s) {
    asm volatile("cp.async.ca.shared.global [%0], [%1], 16;" :: "r"(d), "l"(s) : "memory");
}
#define CP_COMMIT() asm volatile("cp.async.commit_group;" ::: "memory")
template<int N> __device__ __forceinline__ void cp_wait() {
    asm volatile("cp.async.wait_group %0;" :: "n"(N) : "memory");
}
#define LD2(r0, r1, ba) asm volatile("ld.shared.v2.u32 {%0,%1}, [%2];" : "=r"(r0), "=r"(r1) : "r"(ba))

// pack two floats into f16x2 (x0 in low half)
__device__ __forceinline__ uint32_t packh2(float x0, float x1) {
    uint32_t u;
    asm("cvt.rn.f16x2.f32 %0, %1, %2;" : "=r"(u) : "f"(x1), "f"(x0));
    return u;
}
__device__ __forceinline__ void mmaf16(float c[4], const uint32_t a[4], const uint32_t b[2]) {
    asm volatile(
        "mma.sync.aligned.m16n8k16.row.col.f32.f16.f16.f32 "
        "{%0,%1,%2,%3}, {%4,%5,%6,%7}, {%8,%9}, {%0,%1,%2,%3};"
        : "+f"(c[0]), "+f"(c[1]), "+f"(c[2]), "+f"(c[3])
        : "r"(a[0]), "r"(a[1]), "r"(a[2]), "r"(a[3]), "r"(b[0]), "r"(b[1]));
}
__device__ __forceinline__ float silu(float x) { return x / (1.0f + __expf(-x)); }

// k-pair permutation within 8-pair groups (same on A and B storage)
__device__ __forceinline__ int kperm(int p) {
    int l = p & 7;
    return (p & ~7) | ((l < 4) ? (l << 1) : (((l - 4) << 1) | 1));
}

#define INV2048 4.8828125e-4f

// smem u32/float offsets
#define O_XF    0        // fp32 residual 64 x 260
#define O_XH    16640    // act plane 64 x 136 u32 (f16x2)
#define O_HH    25344    // h plane 64 x 136 u32
#define O_WB    34048    // 2 x (256 x 40 u32): [16 hi | 16 lo | 8 pad]
#define O_CV    54528
#define O_B1    54784
#define O_GA    55040
#define O_BE    55296
#define O_B2    55552
#define O_SRS   55808    // 64 x 8
#define O_SRQ   56320
#define O_MU    56832
#define O_RS    56896
#define O_FEAT  56960    // 64 x 6
#define SMEM_U32 57344
#define SMEM_BYTES (SMEM_U32*4)

// ============ weight transpose + exact fp16 hi/lo split + k-pair perm ============
__global__ void splitw_kernel(const float* __restrict__ ly_w1,
                              const float* __restrict__ ly_w2,
                              const float* __restrict__ out_w1)
{
    __shared__ float ts[32][33];   // ts[k_local][n_local]
    int m = blockIdx.x >> 6, tile = blockIdx.x & 63;
    const float* src; uint32_t *dh, *dl; int N = 256;
    if (m < 4)      { src = ly_w1 + m*65536;     dh = g_w1h + m*32768; dl = g_w1l + m*32768; }
    else if (m < 8) { src = ly_w2 + (m-4)*65536; dh = g_w2h + (m-4)*32768; dl = g_w2l + (m-4)*32768; }
    else            { src = out_w1;              dh = g_owh; dl = g_owl; N = 128; }
    int tn = (tile & 7) * 32, tk = (tile >> 3) * 32;
    if (tn >= N) return;
    int lx = threadIdx.x & 31, ly = threadIdx.x >> 5;
    #pragma unroll
    for (int i = 0; i < 32; i += 8) ts[ly+i][lx] = src[(tk+ly+i)*N + tn + lx];
    __syncthreads();
    int kk = lx & 15; bool ishi = lx < 16;
    int kkp = kperm(kk);
    #pragma unroll
    for (int i = 0; i < 32; i += 8) {
        int nl = ly + i;
        float x0 = ts[2*kk][nl], x1 = ts[2*kk+1][nl];
        __half2 hh = __floats2half2_rn(x0, x1);
        float h0 = __low2float(hh), h1 = __high2float(hh);
        __half2 llv = __floats2half2_rn((x0 - h0)*2048.f, (x1 - h1)*2048.f);
        int idx = (tn + nl)*128 + (tk >> 1) + kkp;
        if (ishi) dh[idx] = *reinterpret_cast<uint32_t*>(&hh);
        else      dl[idx] = *reinterpret_cast<uint32_t*>(&llv);
    }
}

// ============ time embedding ============
__global__ void temb_kernel(const int* __restrict__ timesteps,
                            const float* __restrict__ te_w1, const float* __restrict__ te_b1,
                            const float* __restrict__ te_w2, const float* __restrict__ te_b2,
                            const float* __restrict__ tp_w,  const float* __restrict__ tp_b)
{
    __shared__ float emb[128], h1[512], h2[512];
    int b = blockIdx.x, t = threadIdx.x;
    if (t < 64) {
        float fr = expf((float)t * (-logf(10000.0f) / 63.0f));
        float an = (float)timesteps[b] * fr;
        emb[t] = sinf(an); emb[t+64] = cosf(an);
    }
    __syncthreads();
    { float a = te_b1[t];
      #pragma unroll 4
      for (int k = 0; k < 128; k++) a = fmaf(emb[k], te_w1[k*512+t], a);
      h1[t] = a / (1.0f + expf(-a)); }
    __syncthreads();
    { float a = te_b2[t];
      #pragma unroll 4
      for (int k = 0; k < 512; k++) a = fmaf(h1[k], te_w2[k*512+t], a);
      h2[t] = a; }
    __syncthreads();
    if (t < 256) {
        float a = tp_b[t];
        #pragma unroll 4
        for (int k = 0; k < 512; k++) a = fmaf(h2[k], tp_w[k*256+t], a);
        g_tproj[b*256+t] = a;
    }
}

// ============ nearest neighbor (dual comparator chains) ============
#define TSZ 2048
__global__ void nn_kernel(const float* __restrict__ noisy, const float* __restrict__ target)
{
    __shared__ float4 ts[TSZ];
    int b = blockIdx.x >> 8, chunk = (blockIdx.x >> 2) & 63, slice = blockIdx.x & 3;
    int t = threadIdx.x;
    const float4* tg4 = (const float4*)(target + ((size_t)b*NN + (size_t)slice*TSZ) * 3);
    for (int p4 = t; p4 < TSZ/4; p4 += 128) {
        float4 v0 = tg4[3*p4], v1 = tg4[3*p4+1], v2 = tg4[3*p4+2];
        ts[4*p4+0] = make_float4(v0.x, v0.y, v0.z, 0.5f*(v0.x*v0.x + v0.y*v0.y + v0.z*v0.z));
        ts[4*p4+1] = make_float4(v0.w, v1.x, v1.y, 0.5f*(v0.w*v0.w + v1.x*v1.x + v1.y*v1.y));
        ts[4*p4+2] = make_float4(v1.z, v1.w, v2.x, 0.5f*(v1.z*v1.z + v1.w*v1.w + v2.x*v2.x));
        ts[4*p4+3] = make_float4(v2.y, v2.z, v2.w, 0.5f*(v2.y*v2.y + v2.z*v2.z + v2.w*v2.w));
    }
    __syncthreads();
    int p = chunk*128 + t;
    const float* q = noisy + ((size_t)b*NN + p) * 3;
    float qx = -q[0], qy = -q[1], qz = -q[2];
    float best0 = INFINITY, best1 = INFINITY; int b0 = 0, b1 = 1;
    #pragma unroll 4
    for (int j = 0; j < TSZ; j += 2) {
        float4 v0 = ts[j], v1 = ts[j+1];
        float e0 = fmaf(qx, v0.x, v0.w); e0 = fmaf(qy, v0.y, e0); e0 = fmaf(qz, v0.z, e0);
        float e1 = fmaf(qx, v1.x, v1.w); e1 = fmaf(qy, v1.y, e1); e1 = fmaf(qz, v1.z, e1);
        if (e0 < best0) { best0 = e0; b0 = j; }
        if (e1 < best1) { best1 = e1; b1 = j+1; }
    }
    // merge preserving first-min semantics (b0 < b1 within pair, so tie -> chain0 unless b1 < b0 impossible for equal pairs across iterations)
    float best = best0; int bidx = b0;
    if (best1 < best0 || (best1 == best0 && b1 < b0)) { best = best1; bidx = b1; }
    int pi = b*NN + p;
    g_pbest[slice*(BB*NN) + pi] = best;
    g_pidx [slice*(BB*NN) + pi] = slice*TSZ + bidx;
}

// ============ fused fp16 weight-pair MLP ============
__device__ __forceinline__ void loadW(uint32_t* smu, int buf,
                                      const uint32_t* __restrict__ gh,
                                      const uint32_t* __restrict__ gl,
                                      int kc, int nRows, int t)
{
    uint32_t base = smem_to_u32(smu + O_WB + buf*10240);
    int tot = nRows*8;
    #pragma unroll
    for (int i = t; i < tot; i += 512) {
        int n = i >> 3, j = i & 7;
        if (j < 4) cp_async16(base + (uint32_t)((n*40 + j*4)*4),          gh + n*128 + kc*16 + j*4);
        else       cp_async16(base + (uint32_t)((n*40 + 16 + (j-4)*4)*4), gl + n*128 + kc*16 + (j-4)*4);
    }
}

// NT n8-tiles per warp: 4 => N=256 (8 n-warps), 2 => N=128. Tile kc=0 pre-issued.
template<int NT>
__device__ __forceinline__ void gemm_f16p(uint32_t* smu, uint32_t su, int Ao,
                                          const uint32_t* __restrict__ gh,
                                          const uint32_t* __restrict__ gl,
                                          int nRows, float ch[2][NT][4], float cl[2][NT][4],
                                          int t, int wm, int wn, int g, int tt)
{
    #pragma unroll 1
    for (int kc = 0; kc < 8; kc++) {
        __syncthreads();                       // prev buffer consumers done (also publishes A-plane writes on kc=0)
        if (kc < 7) { loadW(smu, (kc+1)&1, gh, gl, kc+1, nRows, t); CP_COMMIT(); cp_wait<1>(); }
        else cp_wait<0>();
        __syncthreads();                       // tile kc visible
        uint32_t WB = su + (uint32_t)((O_WB + (kc&1)*10240)*4);
        uint32_t a[2][2][4], bh[2][NT][2], bl[2][NT][2];
        #pragma unroll
        for (int ks = 0; ks < 2; ks++) {
            int cb = kc*16 + ks*8 + 2*tt;
            #pragma unroll
            for (int mi = 0; mi < 2; mi++) {
                int r = wm*32 + mi*16 + g;
                LD2(a[ks][mi][0], a[ks][mi][2], su + (uint32_t)((Ao + r*136 + cb)*4));
                LD2(a[ks][mi][1], a[ks][mi][3], su + (uint32_t)((Ao + (r+8)*136 + cb)*4));
            }
            #pragma unroll
            for (int nt = 0; nt < NT; nt++) {
                int n = wn*(NT*8) + nt*8 + g;
                uint32_t ib = WB + (uint32_t)((n*40 + ks*8 + 2*tt)*4);
                LD2(bh[ks][nt][0], bh[ks][nt][1], ib);
                LD2(bl[ks][nt][0], bl[ks][nt][1], ib + 64);
            }
        }
        #pragma unroll
        for (int ks = 0; ks < 2; ks++)
            #pragma unroll
            for (int mi = 0; mi < 2; mi++)
                #pragma unroll
                for (int nt = 0; nt < NT; nt++) {
                    mmaf16(ch[mi][nt], a[ks][mi], bh[ks][nt]);
                    mmaf16(cl[mi][nt], a[ks][mi], bl[ks][nt]);
                }
    }
    __syncthreads();
}

__global__ __launch_bounds__(512, 1)
void mlp_f16(const float* __restrict__ noisy, const float* __restrict__ target,
             const float* __restrict__ in_w,  const float* __restrict__ in_b,
             const float* __restrict__ ly_b1, const float* __restrict__ ly_g,
             const float* __restrict__ ly_be, const float* __restrict__ ly_b2,
             const float* __restrict__ out_b1, const float* __restrict__ out_w2,
             const float* __restrict__ out_b2, float* __restrict__ out)
{
    extern __shared__ float sm[];
    uint32_t* smu = (uint32_t*)sm;
    uint32_t su = smem_to_u32(sm);
    int t = threadIdx.x, lane = t & 31, w = t >> 5;
    int wm = w & 1, wn = w >> 1;           // warp grid 2(M) x 8(N)
    int g = lane >> 2, tt = lane & 3;
    int b = blockIdx.x >> 7, row0 = (blockIdx.x & 127) << 6;

    float* xf   = sm + O_XF;
    float* feat = sm + O_FEAT;

    // stage constants; pre-issue W1 layer0 tile0; fused nn_reduce
    if (t < 256) sm[O_CV + t] = in_b[t] + g_tproj[b*256 + t];
    loadW(smu, 0, g_w1h, g_w1l, 0, 256, t); CP_COMMIT();
    if (t < 64) {
        int pi = b*NN + row0 + t;
        float best = g_pbest[pi]; int bi = g_pidx[pi];
        #pragma unroll
        for (int s = 1; s < 4; s++) {
            float vv = g_pbest[s*(BB*NN) + pi];
            if (vv < best) { best = vv; bi = g_pidx[s*(BB*NN) + pi]; }
        }
        const float* tc = target + ((size_t)b*NN + bi)*3;
        feat[t*6+0] = noisy[(size_t)pi*3+0]; feat[t*6+1] = noisy[(size_t)pi*3+1]; feat[t*6+2] = noisy[(size_t)pi*3+2];
        feat[t*6+3] = tc[0]; feat[t*6+4] = tc[1]; feat[t*6+5] = tc[2];
    }
    __syncthreads();

    // ---- input build: x = feat @ in_w + (in_b + tproj) -> xf fp32 + XH f16 plane ----
    {
        int row = t >> 3, q = t & 7;
        float f[6];
        #pragma unroll
        for (int k = 0; k < 6; k++) f[k] = feat[row*6 + k];
        #pragma unroll
        for (int c4 = 0; c4 < 8; c4++) {
            int col = q*32 + c4*4;
            float4 a = *(const float4*)(sm + O_CV + col);
            #pragma unroll
            for (int k = 0; k < 6; k++) {
                float4 wv = *(const float4*)(in_w + k*256 + col);
                a.x = fmaf(f[k], wv.x, a.x); a.y = fmaf(f[k], wv.y, a.y);
                a.z = fmaf(f[k], wv.z, a.z); a.w = fmaf(f[k], wv.w, a.w);
            }
            *(float4*)(xf + row*260 + col) = a;
            int p = col >> 1;
            smu[O_XH + row*136 + kperm(p)]   = packh2(a.x, a.y);
            smu[O_XH + row*136 + kperm(p+1)] = packh2(a.z, a.w);
        }
    }
    // gemm's first __syncthreads() publishes the plane writes

    float v[2][4][4];
    // ---- 4 residual layers ----
    #pragma unroll 1
    for (int lay = 0; lay < 4; lay++) {
        if (t < 256) {
            sm[O_B1 + t] = ly_b1[lay*256 + t]; sm[O_GA + t] = ly_g [lay*256 + t];
            sm[O_BE + t] = ly_be[lay*256 + t]; sm[O_B2 + t] = ly_b2[lay*256 + t];
        }

        // GEMM1: D = x @ W1
        float ch[2][4][4], cl[2][4][4];
        #pragma unroll
        for (int mi = 0; mi < 2; mi++)
            #pragma unroll
            for (int nt = 0; nt < 4; nt++)
                #pragma unroll
                for (int e = 0; e < 4; e++) { ch[mi][nt][e] = 0.f; cl[mi][nt][e] = 0.f; }
        gemm_f16p<4>(smu, su, O_XH, g_w1h + lay*32768, g_w1l + lay*32768, 256, ch, cl, t, wm, wn, g, tt);

        // pre-issue GEMM2 tile0 (overlaps epilogue1)
        loadW(smu, 0, g_w2h + lay*32768, g_w2l + lay*32768, 0, 256, t); CP_COMMIT();

        // epilogue1: combine + b1, LN stats
        float S[2][2] = {{0,0},{0,0}}, Q[2][2] = {{0,0},{0,0}};
        #pragma unroll
        for (int mi = 0; mi < 2; mi++)
            #pragma unroll
            for (int nt = 0; nt < 4; nt++) {
                int bc = wn*32 + nt*8 + 2*tt;
                float b0 = sm[O_B1 + bc], b1v = sm[O_B1 + bc + 1];
                float v0 = fmaf(cl[mi][nt][0], INV2048, ch[mi][nt][0]) + b0;
                float v1 = fmaf(cl[mi][nt][1], INV2048, ch[mi][nt][1]) + b1v;
                float v2 = fmaf(cl[mi][nt][2], INV2048, ch[mi][nt][2]) + b0;
                float v3 = fmaf(cl[mi][nt][3], INV2048, ch[mi][nt][3]) + b1v;
                v[mi][nt][0]=v0; v[mi][nt][1]=v1; v[mi][nt][2]=v2; v[mi][nt][3]=v3;
                S[mi][0] += v0 + v1; Q[mi][0] = fmaf(v0,v0,fmaf(v1,v1,Q[mi][0]));
                S[mi][1] += v2 + v3; Q[mi][1] = fmaf(v2,v2,fmaf(v3,v3,Q[mi][1]));
            }
        #pragma unroll
        for (int mi = 0; mi < 2; mi++)
            #pragma unroll
            for (int h = 0; h < 2; h++) {
                float s = S[mi][h], q = Q[mi][h];
                s += __shfl_xor_sync(~0u, s, 1); s += __shfl_xor_sync(~0u, s, 2);
                q += __shfl_xor_sync(~0u, q, 1); q += __shfl_xor_sync(~0u, q, 2);
                if (tt == 0) {
                    int row = wm*32 + mi*16 + h*8 + g;
                    sm[O_SRS + row*8 + wn] = s;
                    sm[O_SRQ + row*8 + wn] = q;
                }
            }
        __syncthreads();
        if (t < 64) {
            float s = 0.f, q = 0.f;
            #pragma unroll
            for (int i = 0; i < 8; i++) { s += sm[O_SRS + t*8 + i]; q += sm[O_SRQ + t*8 + i]; }
            float mu = s * (1.f/256.f);
            sm[O_RS + t] = rsqrtf(fmaf(-mu, mu, q * (1.f/256.f)) + 1e-5f);
            sm[O_MU + t] = mu;
        }
        __syncthreads();
        // LN + SiLU -> h plane (f16, perm'd k)
        #pragma unroll
        for (int mi = 0; mi < 2; mi++)
            #pragma unroll
            for (int h = 0; h < 2; h++) {
                int row = wm*32 + mi*16 + h*8 + g;
                float mu = sm[O_MU + row], rs = sm[O_RS + row];
                #pragma unroll
                for (int nt = 0; nt < 4; nt++) {
                    int bc = wn*32 + nt*8 + 2*tt;
                    float h0 = silu(fmaf((v[mi][nt][2*h]   - mu)*rs, sm[O_GA + bc],   sm[O_BE + bc]));
                    float h1 = silu(fmaf((v[mi][nt][2*h+1] - mu)*rs, sm[O_GA + bc+1], sm[O_BE + bc+1]));
                    smu[O_HH + row*136 + kperm(bc >> 1)] = packh2(h0, h1);
                }
            }

        // GEMM2: D = h @ W2 (tile0 pre-issued; first sync publishes h writes)
        #pragma unroll
        for (int mi = 0; mi < 2; mi++)
            #pragma unroll
            for (int nt = 0; nt < 4; nt++)
                #pragma unroll
                for (int e = 0; e < 4; e++) { ch[mi][nt][e] = 0.f; cl[mi][nt][e] = 0.f; }
        gemm_f16p<4>(smu, su, O_HH, g_w2h + lay*32768, g_w2l + lay*32768, 256, ch, cl, t, wm, wn, g, tt);

        // pre-issue next tile0 (next layer W1 or head) — overlaps epilogue2
        if (lay < 3) loadW(smu, 0, g_w1h + (lay+1)*32768, g_w1l + (lay+1)*32768, 0, 256, t);
        else         loadW(smu, 0, g_owh, g_owl, 0, 128, t);
        CP_COMMIT();

        // epilogue2: x(fp32) += D + b2; refresh act plane
        #pragma unroll
        for (int mi = 0; mi < 2; mi++)
            #pragma unroll
            for (int h = 0; h < 2; h++) {
                int row = wm*32 + mi*16 + h*8 + g;
                #pragma unroll
                for (int nt = 0; nt < 4; nt++) {
                    int bc = wn*32 + nt*8 + 2*tt;
                    float2* px = (float2*)(xf + row*260 + bc);
                    float2 xv = *px;
                    xv.x += fmaf(cl[mi][nt][2*h],   INV2048, ch[mi][nt][2*h])   + sm[O_B2 + bc];
                    xv.y += fmaf(cl[mi][nt][2*h+1], INV2048, ch[mi][nt][2*h+1]) + sm[O_B2 + bc + 1];
                    *px = xv;
                    smu[O_XH + row*136 + kperm(bc >> 1)] = packh2(xv.x, xv.y);
                }
            }
    }

    // ---- head GEMM: D = x @ out_w1 (N=128, tile0 pre-issued) ----
    {
        float ch[2][2][4], cl[2][2][4];
        #pragma unroll
        for (int mi = 0; mi < 2; mi++)
            #pragma unroll
            for (int nt = 0; nt < 2; nt++)
                #pragma unroll
                for (int e = 0; e < 4; e++) { ch[mi][nt][e] = 0.f; cl[mi][nt][e] = 0.f; }
        gemm_f16p<2>(smu, su, O_XH, g_owh, g_owl, 128, ch, cl, t, wm, wn, g, tt);

        // y1 = silu(D + b1) -> plain fp32 [64][132] in XF region
        #pragma unroll
        for (int mi = 0; mi < 2; mi++)
            #pragma unroll
            for (int h = 0; h < 2; h++) {
                int row = wm*32 + mi*16 + h*8 + g;
                #pragma unroll
                for (int nt = 0; nt < 2; nt++) {
                    int bc = wn*16 + nt*8 + 2*tt;
                    float v0 = fmaf(cl[mi][nt][2*h],   INV2048, ch[mi][nt][2*h])   + out_b1[bc];
                    float v1 = fmaf(cl[mi][nt][2*h+1], INV2048, ch[mi][nt][2*h+1]) + out_b1[bc+1];
                    xf[row*132 + bc]     = silu(v0);
                    xf[row*132 + bc + 1] = silu(v1);
                }
            }
    }
    __syncthreads();

    // ---- final: score = y1 @ out_w2 + out_b2 (128 -> 3, fp32) ----
    if (t < 192) {
        int rr = t / 3, p = t - rr*3;
        float a = out_b2[p];
        const float* y = xf + rr*132;
        #pragma unroll 8
        for (int k = 0; k < 128; k++) a = fmaf(y[k], out_w2[k*3 + p], a);
        out[(size_t)((b*NN + row0 + rr)*3 + p)] = a;
    }
}

// =====================================================================
extern "C" void kernel_launch(void* const* d_in, const int* in_sizes, int n_in,
                              void* d_out, int out_size)
{
    const float* noisy  = (const float*)d_in[0];
    const float* target = (const float*)d_in[1];
    const int*   tsteps = (const int*)  d_in[2];
    const float* te_w1  = (const float*)d_in[3];
    const float* te_b1  = (const float*)d_in[4];
    const float* te_w2  = (const float*)d_in[5];
    const float* te_b2  = (const float*)d_in[6];
    const float* tp_w   = (const float*)d_in[7];
    const float* tp_b   = (const float*)d_in[8];
    const float* in_w   = (const float*)d_in[9];
    const float* in_b   = (const float*)d_in[10];
    const float* ly_w1  = (const float*)d_in[11];
    const float* ly_b1  = (const float*)d_in[12];
    const float* ly_g   = (const float*)d_in[13];
    const float* ly_be  = (const float*)d_in[14];
    const float* ly_w2  = (const float*)d_in[15];
    const float* ly_b2  = (const float*)d_in[16];
    const float* out_w1 = (const float*)d_in[17];
    const float* out_b1 = (const float*)d_in[18];
    const float* out_w2 = (const float*)d_in[19];
    const float* out_b2 = (const float*)d_in[20];
    float* out = (float*)d_out;

    cudaFuncSetAttribute(mlp_f16, cudaFuncAttributeMaxDynamicSharedMemorySize, SMEM_BYTES);

    splitw_kernel<<<576, 256>>>(ly_w1, ly_w2, out_w1);
    temb_kernel<<<4, 512>>>(tsteps, te_w1, te_b1, te_w2, te_b2, tp_w, tp_b);
    nn_kernel<<<1024, 128>>>(noisy, target);
    mlp_f16<<<512, 512, SMEM_BYTES>>>(noisy, target, in_w, in_b,
                                      ly_b1, ly_g, ly_be, ly_b2,
                                      out_b1, out_w2, out_b2, out);
}